// round 1
// baseline (speedup 1.0000x reference)
#include <cuda_runtime.h>
#include <math.h>

// Problem constants
#define BB   32
#define LL   400
#define HH   512
#define NHH  8
#define DHH  64
#define KW   7
#define NCC  4
#define MM   (BB * LL)      // 12800 tokens
#define H3   (3 * HH)       // 1536

// ---------------------------------------------------------------------------
// Scratch (static device arrays; no allocations allowed)
// ---------------------------------------------------------------------------
__device__ float g_norm  [MM * HH];                       // 6.55M
__device__ float g_dwout [MM * HH];                       // 6.55M
__device__ float g_qkv   [MM * H3];                       // 19.66M
__device__ float g_scores[(size_t)BB * NHH * LL * LL];    // 40.96M (164 MB)
__device__ float g_attout[MM * HH];                       // 6.55M

// ---------------------------------------------------------------------------
// out = x + positional encoding
// ---------------------------------------------------------------------------
__global__ void add_pe_kernel(const float* __restrict__ x, float* __restrict__ out) {
    int idx = blockIdx.x * blockDim.x + threadIdx.x;
    if (idx >= MM * HH) return;
    int h = idx & (HH - 1);
    int l = (idx / HH) % LL;
    // div[i] = exp(-(2i) * ln(10000)/H); for column h use 2i = h & ~1
    float freq = expf(-(float)(h & ~1) * (9.210340371976184f / (float)HH));
    float a = (float)l * freq;
    float pe = (h & 1) ? cosf(a) : sinf(a);
    out[idx] = x[idx] + pe;
}

// ---------------------------------------------------------------------------
// LayerNorm over last dim (H=512). One block per row, 128 threads, float4.
// Two-pass (mean, then centered variance) for numerical safety.
// ---------------------------------------------------------------------------
__global__ void ln_kernel(const float* __restrict__ in, float* __restrict__ out,
                          const float* __restrict__ gw, const float* __restrict__ gb) {
    int row = blockIdx.x;
    int t   = threadIdx.x;  // 128
    const float4* p = (const float4*)(in + (size_t)row * HH);
    float4 v = p[t];

    __shared__ float sh[4];

    float s = v.x + v.y + v.z + v.w;
    #pragma unroll
    for (int o = 16; o > 0; o >>= 1) s += __shfl_down_sync(0xffffffffu, s, o);
    if ((t & 31) == 0) sh[t >> 5] = s;
    __syncthreads();
    float mean = (sh[0] + sh[1] + sh[2] + sh[3]) * (1.0f / HH);
    __syncthreads();

    float dx = v.x - mean, dy = v.y - mean, dz = v.z - mean, dw = v.w - mean;
    float q = dx * dx + dy * dy + dz * dz + dw * dw;
    #pragma unroll
    for (int o = 16; o > 0; o >>= 1) q += __shfl_down_sync(0xffffffffu, q, o);
    if ((t & 31) == 0) sh[t >> 5] = q;
    __syncthreads();
    float var  = (sh[0] + sh[1] + sh[2] + sh[3]) * (1.0f / HH);
    float rstd = rsqrtf(var + 1e-5f);

    float4 g4 = ((const float4*)gw)[t];
    float4 b4 = ((const float4*)gb)[t];
    float4 o4;
    o4.x = dx * rstd * g4.x + b4.x;
    o4.y = dy * rstd * g4.y + b4.y;
    o4.z = dz * rstd * g4.z + b4.z;
    o4.w = dw * rstd * g4.w + b4.w;
    ((float4*)(out + (size_t)row * HH))[t] = o4;
}

// ---------------------------------------------------------------------------
// Depthwise conv K=7, pad 3, over (B,L,C) layout (channels fastest).
// ---------------------------------------------------------------------------
__global__ void dwconv_kernel(const float* __restrict__ norm, float* __restrict__ outb,
                              const float* __restrict__ w, const float* __restrict__ bias) {
    int idx = blockIdx.x * blockDim.x + threadIdx.x;
    if (idx >= MM * HH) return;
    int c = idx & (HH - 1);
    int l = (idx / HH) % LL;
    int b = idx / (HH * LL);
    const float* wr = w + c * KW;
    float acc = bias[c];
    #pragma unroll
    for (int k = 0; k < KW; k++) {
        int ll = l + k - 3;
        if (ll >= 0 && ll < LL)
            acc += norm[((size_t)b * LL + ll) * HH + c] * wr[k];
    }
    outb[idx] = acc;
}

// ---------------------------------------------------------------------------
// Tiled fp32 GEMM: C[m,n] = act( sum_k A[m,k]*W[n,k] + bias[n] ) (+ R[m,n])
// BM=BN=64, BK=16, 256 threads, 4x4 micro-tile, float4 smem reads.
// M,N,K all divide the tile sizes for every call in this kernel.
// ---------------------------------------------------------------------------
template <bool RELU, bool RES>
__global__ void gemm_kernel(const float* __restrict__ A, const float* __restrict__ W,
                            const float* __restrict__ bias, const float* __restrict__ R,
                            float* __restrict__ C, int Md, int Nd, int Kd) {
    __shared__ float As[16][64];
    __shared__ float Ws[16][64];

    int tid = threadIdx.x;
    int m0 = blockIdx.y * 64;
    int n0 = blockIdx.x * 64;

    int lr = tid >> 2;          // 0..63
    int lk = (tid & 3) * 4;     // 0,4,8,12

    int ty4 = (tid >> 4) * 4;   // m within tile
    int tx4 = (tid & 15) * 4;   // n within tile

    float acc[4][4] = {};

    for (int k0 = 0; k0 < Kd; k0 += 16) {
        float4 a = *(const float4*)&A[(size_t)(m0 + lr) * Kd + k0 + lk];
        float4 w = *(const float4*)&W[(size_t)(n0 + lr) * Kd + k0 + lk];
        As[lk + 0][lr] = a.x; As[lk + 1][lr] = a.y; As[lk + 2][lr] = a.z; As[lk + 3][lr] = a.w;
        Ws[lk + 0][lr] = w.x; Ws[lk + 1][lr] = w.y; Ws[lk + 2][lr] = w.z; Ws[lk + 3][lr] = w.w;
        __syncthreads();
        #pragma unroll
        for (int kk = 0; kk < 16; kk++) {
            float4 av = *(const float4*)&As[kk][ty4];
            float4 wv = *(const float4*)&Ws[kk][tx4];
            float ar[4] = {av.x, av.y, av.z, av.w};
            float wr[4] = {wv.x, wv.y, wv.z, wv.w};
            #pragma unroll
            for (int i = 0; i < 4; i++)
                #pragma unroll
                for (int j = 0; j < 4; j++)
                    acc[i][j] += ar[i] * wr[j];
        }
        __syncthreads();
    }

    #pragma unroll
    for (int i = 0; i < 4; i++) {
        int m = m0 + ty4 + i;
        #pragma unroll
        for (int j = 0; j < 4; j++) {
            int n = n0 + tx4 + j;
            float v = acc[i][j] + bias[n];
            if (RELU) v = fmaxf(v, 0.0f);
            if (RES)  v += R[(size_t)m * Nd + n];
            C[(size_t)m * Nd + n] = v;
        }
    }
}

// ---------------------------------------------------------------------------
// Attention scores: S[bh,q,k] = dot(q_row, k_row)/8, mask -> -1e9
// Tiles of 16x16, d=64 in smem. Grid: (B*NH, 25, 25).
// ---------------------------------------------------------------------------
__global__ void scores_kernel(const float* __restrict__ qkv, const int* __restrict__ mask,
                              float* __restrict__ S) {
    int bh = blockIdx.x;
    int b  = bh >> 3;
    int h  = bh & 7;
    int q0 = blockIdx.y * 16;
    int k0 = blockIdx.z * 16;

    __shared__ float Qs[16][65];
    __shared__ float Ks[16][65];

    int tid = threadIdx.x;          // 256
    int r   = tid >> 4;             // 0..15
    int c4  = (tid & 15) * 4;       // 0..60

    const float* qp = qkv + ((size_t)(b * LL + q0 + r)) * H3 + h * DHH + c4;
    const float* kp = qkv + ((size_t)(b * LL + k0 + r)) * H3 + HH + h * DHH + c4;
    float4 qv = *(const float4*)qp;
    float4 kv = *(const float4*)kp;
    Qs[r][c4 + 0] = qv.x; Qs[r][c4 + 1] = qv.y; Qs[r][c4 + 2] = qv.z; Qs[r][c4 + 3] = qv.w;
    Ks[r][c4 + 0] = kv.x; Ks[r][c4 + 1] = kv.y; Ks[r][c4 + 2] = kv.z; Ks[r][c4 + 3] = kv.w;
    __syncthreads();

    int qy = tid >> 4;
    int kx = tid & 15;
    float acc = 0.0f;
    #pragma unroll
    for (int d = 0; d < DHH; d++) acc += Qs[qy][d] * Ks[kx][d];
    acc *= 0.125f;  // 1/sqrt(64)
    if (mask[b * LL + k0 + kx] <= 0) acc = -1e9f;
    S[((size_t)bh * LL + (q0 + qy)) * LL + (k0 + kx)] = acc;
}

// ---------------------------------------------------------------------------
// Row softmax over k (L=400). One block per (bh, q), 128 threads.
// ---------------------------------------------------------------------------
__global__ void softmax_kernel(float* __restrict__ S) {
    size_t row = blockIdx.x;
    float* p = S + row * LL;
    int t = threadIdx.x;

    __shared__ float sh[4];

    float m = -1e30f;
    for (int i = t; i < LL; i += 128) m = fmaxf(m, p[i]);
    #pragma unroll
    for (int o = 16; o > 0; o >>= 1) m = fmaxf(m, __shfl_down_sync(0xffffffffu, m, o));
    if ((t & 31) == 0) sh[t >> 5] = m;
    __syncthreads();
    m = fmaxf(fmaxf(sh[0], sh[1]), fmaxf(sh[2], sh[3]));
    __syncthreads();

    float s = 0.0f;
    for (int i = t; i < LL; i += 128) s += expf(p[i] - m);
    #pragma unroll
    for (int o = 16; o > 0; o >>= 1) s += __shfl_down_sync(0xffffffffu, s, o);
    if ((t & 31) == 0) sh[t >> 5] = s;
    __syncthreads();
    float inv = 1.0f / (sh[0] + sh[1] + sh[2] + sh[3]);

    for (int i = t; i < LL; i += 128) p[i] = expf(p[i] - m) * inv;
}

// ---------------------------------------------------------------------------
// AV: attout[b, q, h*64+d] = sum_k P[bh,q,k] * V[b,k,h,d]
// Block: (bh, qtile of 32). K streamed in chunks of 64 via smem.
// ---------------------------------------------------------------------------
__global__ void av_kernel(const float* __restrict__ S, const float* __restrict__ qkv,
                          float* __restrict__ attout) {
    int bh = blockIdx.x;
    int b  = bh >> 3;
    int h  = bh & 7;
    int q0 = blockIdx.y * 32;

    __shared__ float Ps[32][64];
    __shared__ float Vs[64][64];

    int tid = threadIdx.x;      // 256
    int tq  = tid >> 3;         // 0..31
    int td  = (tid & 7) * 8;    // 0..56

    float acc[8] = {};

    for (int kt = 0; kt < LL; kt += 64) {
        // load P tile (32x64) with bounds
        for (int i = tid; i < 32 * 64; i += 256) {
            int r = i >> 6, c = i & 63;
            int qq = q0 + r, k = kt + c;
            Ps[r][c] = (qq < LL && k < LL)
                       ? S[((size_t)bh * LL + qq) * LL + k] : 0.0f;
        }
        // load V tile (64x64) with bounds
        for (int i = tid; i < 64 * 64; i += 256) {
            int r = i >> 6, c = i & 63;
            int k = kt + r;
            Vs[r][c] = (k < LL)
                       ? qkv[((size_t)(b * LL + k)) * H3 + 2 * HH + h * DHH + c] : 0.0f;
        }
        __syncthreads();

        #pragma unroll 8
        for (int kk = 0; kk < 64; kk++) {
            float pv = Ps[tq][kk];
            float4 v0 = *(const float4*)&Vs[kk][td];
            float4 v1 = *(const float4*)&Vs[kk][td + 4];
            acc[0] += pv * v0.x; acc[1] += pv * v0.y;
            acc[2] += pv * v0.z; acc[3] += pv * v0.w;
            acc[4] += pv * v1.x; acc[5] += pv * v1.y;
            acc[6] += pv * v1.z; acc[7] += pv * v1.w;
        }
        __syncthreads();
    }

    if (q0 + tq < LL) {
        float* o = attout + ((size_t)(b * LL + q0 + tq)) * HH + h * DHH + td;
        #pragma unroll
        for (int j = 0; j < 8; j++) o[j] = acc[j];
    }
}

// ---------------------------------------------------------------------------
// Launch
// ---------------------------------------------------------------------------
extern "C" void kernel_launch(void* const* d_in, const int* in_sizes, int n_in,
                              void* d_out, int out_size) {
    const float* x         = (const float*)d_in[0];
    const int*   mask      = (const int*)  d_in[1];
    const float* conv_ln_g = (const float*)d_in[2];
    const float* conv_ln_b = (const float*)d_in[3];
    const float* dw_w      = (const float*)d_in[4];
    const float* dw_b      = (const float*)d_in[5];
    const float* pw_w      = (const float*)d_in[6];
    const float* pw_b      = (const float*)d_in[7];
    const float* att_ln_g  = (const float*)d_in[8];
    const float* att_ln_b  = (const float*)d_in[9];
    const float* qkv_w     = (const float*)d_in[10];
    const float* qkv_b     = (const float*)d_in[11];
    const float* out_w     = (const float*)d_in[12];
    const float* out_b     = (const float*)d_in[13];
    const float* ff_ln_g   = (const float*)d_in[14];
    const float* ff_ln_b   = (const float*)d_in[15];
    const float* ff_w      = (const float*)d_in[16];
    const float* ff_b      = (const float*)d_in[17];
    float* out = (float*)d_out;

    float *norm, *dwout, *qkv, *S, *attout;
    cudaGetSymbolAddress((void**)&norm,   g_norm);
    cudaGetSymbolAddress((void**)&dwout,  g_dwout);
    cudaGetSymbolAddress((void**)&qkv,    g_qkv);
    cudaGetSymbolAddress((void**)&S,      g_scores);
    cudaGetSymbolAddress((void**)&attout, g_attout);

    const int elems = MM * HH;

    // out = x + pe
    add_pe_kernel<<<(elems + 255) / 256, 256>>>(x, out);

    // conv blocks
    for (int i = 0; i < NCC; i++) {
        ln_kernel<<<MM, 128>>>(out, norm, conv_ln_g + i * HH, conv_ln_b + i * HH);
        dwconv_kernel<<<(elems + 255) / 256, 256>>>(norm, dwout,
                                                    dw_w + i * HH * KW, dw_b + i * HH);
        gemm_kernel<true, true><<<dim3(HH / 64, MM / 64), 256>>>(
            dwout, pw_w + (size_t)i * HH * HH, pw_b + i * HH, out, out, MM, HH, HH);
    }

    // attention
    ln_kernel<<<MM, 128>>>(out, norm, att_ln_g, att_ln_b);
    gemm_kernel<false, false><<<dim3(H3 / 64, MM / 64), 256>>>(
        norm, qkv_w, qkv_b, nullptr, qkv, MM, H3, HH);
    scores_kernel<<<dim3(BB * NHH, LL / 16, LL / 16), 256>>>(qkv, mask, S);
    softmax_kernel<<<BB * NHH * LL, 128>>>(S);
    av_kernel<<<dim3(BB * NHH, (LL + 31) / 32), 256>>>(S, qkv, attout);
    gemm_kernel<false, true><<<dim3(HH / 64, MM / 64), 256>>>(
        attout, out_w, out_b, out, out, MM, HH, HH);

    // feed-forward
    ln_kernel<<<MM, 128>>>(out, norm, ff_ln_g, ff_ln_b);
    gemm_kernel<true, true><<<dim3(HH / 64, MM / 64), 256>>>(
        norm, ff_w, ff_b, out, out, MM, HH, HH);
}

// round 2
// speedup vs baseline: 1.4866x; 1.4866x over previous
#include <cuda_runtime.h>
#include <math.h>

// Problem constants
#define BB   32
#define LL   400
#define HH   512
#define NHH  8
#define DHH  64
#define KW   7
#define NCC  4
#define MM   (BB * LL)      // 12800 tokens
#define H3   (3 * HH)       // 1536

// ---------------------------------------------------------------------------
// Scratch (static device arrays; no allocations allowed)
// ---------------------------------------------------------------------------
__device__ float g_norm  [MM * HH];
__device__ float g_dwout [MM * HH];
__device__ float g_qkv   [MM * H3];
__device__ float g_scores[(size_t)BB * NHH * LL * LL];
__device__ float g_attout[MM * HH];

// ---------------------------------------------------------------------------
// out = x + positional encoding
// ---------------------------------------------------------------------------
__global__ void add_pe_kernel(const float* __restrict__ x, float* __restrict__ out) {
    int idx = blockIdx.x * blockDim.x + threadIdx.x;
    if (idx >= MM * HH) return;
    int h = idx & (HH - 1);
    int l = (idx / HH) % LL;
    float freq = expf(-(float)(h & ~1) * (9.210340371976184f / (float)HH));
    float a = (float)l * freq;
    float pe = (h & 1) ? cosf(a) : sinf(a);
    out[idx] = x[idx] + pe;
}

// ---------------------------------------------------------------------------
// LayerNorm over last dim (H=512). One block per row, 128 threads, float4.
// ---------------------------------------------------------------------------
__global__ void ln_kernel(const float* __restrict__ in, float* __restrict__ out,
                          const float* __restrict__ gw, const float* __restrict__ gb) {
    int row = blockIdx.x;
    int t   = threadIdx.x;  // 128
    const float4* p = (const float4*)(in + (size_t)row * HH);
    float4 v = p[t];

    __shared__ float sh[4];

    float s = v.x + v.y + v.z + v.w;
    #pragma unroll
    for (int o = 16; o > 0; o >>= 1) s += __shfl_down_sync(0xffffffffu, s, o);
    if ((t & 31) == 0) sh[t >> 5] = s;
    __syncthreads();
    float mean = (sh[0] + sh[1] + sh[2] + sh[3]) * (1.0f / HH);
    __syncthreads();

    float dx = v.x - mean, dy = v.y - mean, dz = v.z - mean, dw = v.w - mean;
    float q = dx * dx + dy * dy + dz * dz + dw * dw;
    #pragma unroll
    for (int o = 16; o > 0; o >>= 1) q += __shfl_down_sync(0xffffffffu, q, o);
    if ((t & 31) == 0) sh[t >> 5] = q;
    __syncthreads();
    float var  = (sh[0] + sh[1] + sh[2] + sh[3]) * (1.0f / HH);
    float rstd = rsqrtf(var + 1e-5f);

    float4 g4 = ((const float4*)gw)[t];
    float4 b4 = ((const float4*)gb)[t];
    float4 o4;
    o4.x = dx * rstd * g4.x + b4.x;
    o4.y = dy * rstd * g4.y + b4.y;
    o4.z = dz * rstd * g4.z + b4.z;
    o4.w = dw * rstd * g4.w + b4.w;
    ((float4*)(out + (size_t)row * HH))[t] = o4;
}

// ---------------------------------------------------------------------------
// Depthwise conv K=7, pad 3, over (B,L,C) layout (channels fastest).
// ---------------------------------------------------------------------------
__global__ void dwconv_kernel(const float* __restrict__ norm, float* __restrict__ outb,
                              const float* __restrict__ w, const float* __restrict__ bias) {
    int idx = blockIdx.x * blockDim.x + threadIdx.x;
    if (idx >= MM * HH) return;
    int c = idx & (HH - 1);
    int l = (idx / HH) % LL;
    int b = idx / (HH * LL);
    const float* wr = w + c * KW;
    float acc = bias[c];
    #pragma unroll
    for (int k = 0; k < KW; k++) {
        int ll = l + k - 3;
        if (ll >= 0 && ll < LL)
            acc += norm[((size_t)b * LL + ll) * HH + c] * wr[k];
    }
    outb[idx] = acc;
}

// ---------------------------------------------------------------------------
// tf32 helpers
// ---------------------------------------------------------------------------
__device__ __forceinline__ unsigned f2tf32(float x) {
    unsigned r;
    asm("cvt.rna.tf32.f32 %0, %1;" : "=r"(r) : "f"(x));
    return r;
}

__device__ __forceinline__ void mma_tf32(float* d, const unsigned* a, const unsigned* b) {
    asm volatile(
        "mma.sync.aligned.m16n8k8.row.col.f32.tf32.tf32.f32 "
        "{%0,%1,%2,%3}, {%4,%5,%6,%7}, {%8,%9}, {%0,%1,%2,%3};\n"
        : "+f"(d[0]), "+f"(d[1]), "+f"(d[2]), "+f"(d[3])
        : "r"(a[0]), "r"(a[1]), "r"(a[2]), "r"(a[3]), "r"(b[0]), "r"(b[1]));
}

// ---------------------------------------------------------------------------
// tf32 tensor-core GEMM: C[m,n] = act( sum_k A[m,k]*W[n,k] + bias[n] ) (+ R)
// BM=128, BN=64, BK=16, 256 threads (8 warps, 4x2), warp tile 32x32
// via 2x4 m16n8k8 mma tiles. Smem padded stride 20 (conflict-free frags).
// M%128==0, N%64==0, K%16==0 hold for all call sites.
// ---------------------------------------------------------------------------
template <bool RELU, bool RES>
__global__ void __launch_bounds__(256)
gemm_tf32_kernel(const float* __restrict__ A, const float* __restrict__ W,
                 const float* __restrict__ bias, const float* __restrict__ R,
                 float* __restrict__ C, int Md, int Nd, int Kd) {
    __shared__ unsigned As[128][20];
    __shared__ unsigned Ws[64][20];

    int tid  = threadIdx.x;
    int m0   = blockIdx.y * 128;
    int n0   = blockIdx.x * 64;
    int warp = tid >> 5;
    int lane = tid & 31;
    int wm   = (warp >> 1) * 32;  // 0,32,64,96
    int wn   = (warp & 1) * 32;   // 0,32
    int lg   = lane >> 2;         // 0..7
    int lq   = lane & 3;          // 0..3

    int lrow = tid >> 2;          // 0..63
    int lk   = (tid & 3) * 4;     // 0,4,8,12

    float acc[2][4][4];
    #pragma unroll
    for (int i = 0; i < 2; i++)
        #pragma unroll
        for (int j = 0; j < 4; j++)
            #pragma unroll
            for (int r = 0; r < 4; r++) acc[i][j][r] = 0.0f;

    for (int k0 = 0; k0 < Kd; k0 += 16) {
        float4 av0 = *(const float4*)&A[(size_t)(m0 + lrow)      * Kd + k0 + lk];
        float4 av1 = *(const float4*)&A[(size_t)(m0 + 64 + lrow) * Kd + k0 + lk];
        float4 wv  = *(const float4*)&W[(size_t)(n0 + lrow)      * Kd + k0 + lk];
        As[lrow][lk + 0] = f2tf32(av0.x); As[lrow][lk + 1] = f2tf32(av0.y);
        As[lrow][lk + 2] = f2tf32(av0.z); As[lrow][lk + 3] = f2tf32(av0.w);
        As[64 + lrow][lk + 0] = f2tf32(av1.x); As[64 + lrow][lk + 1] = f2tf32(av1.y);
        As[64 + lrow][lk + 2] = f2tf32(av1.z); As[64 + lrow][lk + 3] = f2tf32(av1.w);
        Ws[lrow][lk + 0] = f2tf32(wv.x); Ws[lrow][lk + 1] = f2tf32(wv.y);
        Ws[lrow][lk + 2] = f2tf32(wv.z); Ws[lrow][lk + 3] = f2tf32(wv.w);
        __syncthreads();

        #pragma unroll
        for (int ks = 0; ks < 2; ks++) {
            int kb = ks * 8;
            unsigned af[2][4], bf[4][2];
            #pragma unroll
            for (int mt = 0; mt < 2; mt++) {
                int mr = wm + mt * 16 + lg;
                af[mt][0] = As[mr][kb + lq];
                af[mt][1] = As[mr + 8][kb + lq];
                af[mt][2] = As[mr][kb + lq + 4];
                af[mt][3] = As[mr + 8][kb + lq + 4];
            }
            #pragma unroll
            for (int nt = 0; nt < 4; nt++) {
                int nr = wn + nt * 8 + lg;
                bf[nt][0] = Ws[nr][kb + lq];
                bf[nt][1] = Ws[nr][kb + lq + 4];
            }
            #pragma unroll
            for (int mt = 0; mt < 2; mt++)
                #pragma unroll
                for (int nt = 0; nt < 4; nt++)
                    mma_tf32(acc[mt][nt], af[mt], bf[nt]);
        }
        __syncthreads();
    }

    // Epilogue: c0,c1 at (row, 2q),(row, 2q+1); c2,c3 at (row+8, ...)
    #pragma unroll
    for (int mt = 0; mt < 2; mt++) {
        #pragma unroll
        for (int half = 0; half < 2; half++) {
            int m = m0 + wm + mt * 16 + lg + half * 8;
            #pragma unroll
            for (int nt = 0; nt < 4; nt++) {
                int n = n0 + wn + nt * 8 + 2 * lq;
                float v0 = acc[mt][nt][half * 2 + 0] + bias[n];
                float v1 = acc[mt][nt][half * 2 + 1] + bias[n + 1];
                if (RELU) { v0 = fmaxf(v0, 0.0f); v1 = fmaxf(v1, 0.0f); }
                if (RES)  { v0 += R[(size_t)m * Nd + n]; v1 += R[(size_t)m * Nd + n + 1]; }
                *(float2*)&C[(size_t)m * Nd + n] = make_float2(v0, v1);
            }
        }
    }
}

// ---------------------------------------------------------------------------
// Attention scores: S[bh,q,k] = dot(q_row, k_row)/8, mask -> -1e9
// ---------------------------------------------------------------------------
__global__ void scores_kernel(const float* __restrict__ qkv, const int* __restrict__ mask,
                              float* __restrict__ S) {
    int bh = blockIdx.x;
    int b  = bh >> 3;
    int h  = bh & 7;
    int q0 = blockIdx.y * 16;
    int k0 = blockIdx.z * 16;

    __shared__ float Qs[16][65];
    __shared__ float Ks[16][65];

    int tid = threadIdx.x;          // 256
    int r   = tid >> 4;
    int c4  = (tid & 15) * 4;

    const float* qp = qkv + ((size_t)(b * LL + q0 + r)) * H3 + h * DHH + c4;
    const float* kp = qkv + ((size_t)(b * LL + k0 + r)) * H3 + HH + h * DHH + c4;
    float4 qv = *(const float4*)qp;
    float4 kv = *(const float4*)kp;
    Qs[r][c4 + 0] = qv.x; Qs[r][c4 + 1] = qv.y; Qs[r][c4 + 2] = qv.z; Qs[r][c4 + 3] = qv.w;
    Ks[r][c4 + 0] = kv.x; Ks[r][c4 + 1] = kv.y; Ks[r][c4 + 2] = kv.z; Ks[r][c4 + 3] = kv.w;
    __syncthreads();

    int qy = tid >> 4;
    int kx = tid & 15;
    float acc = 0.0f;
    #pragma unroll
    for (int d = 0; d < DHH; d++) acc += Qs[qy][d] * Ks[kx][d];
    acc *= 0.125f;
    if (mask[b * LL + k0 + kx] <= 0) acc = -1e9f;
    S[((size_t)bh * LL + (q0 + qy)) * LL + (k0 + kx)] = acc;
}

// ---------------------------------------------------------------------------
// Row softmax over k (L=400).
// ---------------------------------------------------------------------------
__global__ void softmax_kernel(float* __restrict__ S) {
    size_t row = blockIdx.x;
    float* p = S + row * LL;
    int t = threadIdx.x;

    __shared__ float sh[4];

    float m = -1e30f;
    for (int i = t; i < LL; i += 128) m = fmaxf(m, p[i]);
    #pragma unroll
    for (int o = 16; o > 0; o >>= 1) m = fmaxf(m, __shfl_down_sync(0xffffffffu, m, o));
    if ((t & 31) == 0) sh[t >> 5] = m;
    __syncthreads();
    m = fmaxf(fmaxf(sh[0], sh[1]), fmaxf(sh[2], sh[3]));
    __syncthreads();

    float s = 0.0f;
    for (int i = t; i < LL; i += 128) s += expf(p[i] - m);
    #pragma unroll
    for (int o = 16; o > 0; o >>= 1) s += __shfl_down_sync(0xffffffffu, s, o);
    if ((t & 31) == 0) sh[t >> 5] = s;
    __syncthreads();
    float inv = 1.0f / (sh[0] + sh[1] + sh[2] + sh[3]);

    for (int i = t; i < LL; i += 128) p[i] = expf(p[i] - m) * inv;
}

// ---------------------------------------------------------------------------
// AV: attout[b, q, h*64+d] = sum_k P[bh,q,k] * V[b,k,h,d]
// ---------------------------------------------------------------------------
__global__ void av_kernel(const float* __restrict__ S, const float* __restrict__ qkv,
                          float* __restrict__ attout) {
    int bh = blockIdx.x;
    int b  = bh >> 3;
    int h  = bh & 7;
    int q0 = blockIdx.y * 32;

    __shared__ float Ps[32][64];
    __shared__ float Vs[64][64];

    int tid = threadIdx.x;      // 256
    int tq  = tid >> 3;
    int td  = (tid & 7) * 8;

    float acc[8] = {};

    for (int kt = 0; kt < LL; kt += 64) {
        for (int i = tid; i < 32 * 64; i += 256) {
            int r = i >> 6, c = i & 63;
            int qq = q0 + r, k = kt + c;
            Ps[r][c] = (qq < LL && k < LL)
                       ? S[((size_t)bh * LL + qq) * LL + k] : 0.0f;
        }
        for (int i = tid; i < 64 * 64; i += 256) {
            int r = i >> 6, c = i & 63;
            int k = kt + r;
            Vs[r][c] = (k < LL)
                       ? qkv[((size_t)(b * LL + k)) * H3 + 2 * HH + h * DHH + c] : 0.0f;
        }
        __syncthreads();

        #pragma unroll 8
        for (int kk = 0; kk < 64; kk++) {
            float pv = Ps[tq][kk];
            float4 v0 = *(const float4*)&Vs[kk][td];
            float4 v1 = *(const float4*)&Vs[kk][td + 4];
            acc[0] += pv * v0.x; acc[1] += pv * v0.y;
            acc[2] += pv * v0.z; acc[3] += pv * v0.w;
            acc[4] += pv * v1.x; acc[5] += pv * v1.y;
            acc[6] += pv * v1.z; acc[7] += pv * v1.w;
        }
        __syncthreads();
    }

    if (q0 + tq < LL) {
        float* o = attout + ((size_t)(b * LL + q0 + tq)) * HH + h * DHH + td;
        #pragma unroll
        for (int j = 0; j < 8; j++) o[j] = acc[j];
    }
}

// ---------------------------------------------------------------------------
// Launch
// ---------------------------------------------------------------------------
extern "C" void kernel_launch(void* const* d_in, const int* in_sizes, int n_in,
                              void* d_out, int out_size) {
    const float* x         = (const float*)d_in[0];
    const int*   mask      = (const int*)  d_in[1];
    const float* conv_ln_g = (const float*)d_in[2];
    const float* conv_ln_b = (const float*)d_in[3];
    const float* dw_w      = (const float*)d_in[4];
    const float* dw_b      = (const float*)d_in[5];
    const float* pw_w      = (const float*)d_in[6];
    const float* pw_b      = (const float*)d_in[7];
    const float* att_ln_g  = (const float*)d_in[8];
    const float* att_ln_b  = (const float*)d_in[9];
    const float* qkv_w     = (const float*)d_in[10];
    const float* qkv_b     = (const float*)d_in[11];
    const float* out_w     = (const float*)d_in[12];
    const float* out_b     = (const float*)d_in[13];
    const float* ff_ln_g   = (const float*)d_in[14];
    const float* ff_ln_b   = (const float*)d_in[15];
    const float* ff_w      = (const float*)d_in[16];
    const float* ff_b      = (const float*)d_in[17];
    float* out = (float*)d_out;

    float *norm, *dwout, *qkv, *S, *attout;
    cudaGetSymbolAddress((void**)&norm,   g_norm);
    cudaGetSymbolAddress((void**)&dwout,  g_dwout);
    cudaGetSymbolAddress((void**)&qkv,    g_qkv);
    cudaGetSymbolAddress((void**)&S,      g_scores);
    cudaGetSymbolAddress((void**)&attout, g_attout);

    const int elems = MM * HH;

    add_pe_kernel<<<(elems + 255) / 256, 256>>>(x, out);

    for (int i = 0; i < NCC; i++) {
        ln_kernel<<<MM, 128>>>(out, norm, conv_ln_g + i * HH, conv_ln_b + i * HH);
        dwconv_kernel<<<(elems + 255) / 256, 256>>>(norm, dwout,
                                                    dw_w + i * HH * KW, dw_b + i * HH);
        gemm_tf32_kernel<true, true><<<dim3(HH / 64, MM / 128), 256>>>(
            dwout, pw_w + (size_t)i * HH * HH, pw_b + i * HH, out, out, MM, HH, HH);
    }

    ln_kernel<<<MM, 128>>>(out, norm, att_ln_g, att_ln_b);
    gemm_tf32_kernel<false, false><<<dim3(H3 / 64, MM / 128), 256>>>(
        norm, qkv_w, qkv_b, nullptr, qkv, MM, H3, HH);
    scores_kernel<<<dim3(BB * NHH, LL / 16, LL / 16), 256>>>(qkv, mask, S);
    softmax_kernel<<<BB * NHH * LL, 128>>>(S);
    av_kernel<<<dim3(BB * NHH, (LL + 31) / 32), 256>>>(S, qkv, attout);
    gemm_tf32_kernel<false, true><<<dim3(HH / 64, MM / 128), 256>>>(
        attout, out_w, out_b, out, out, MM, HH, HH);

    ln_kernel<<<MM, 128>>>(out, norm, ff_ln_g, ff_ln_b);
    gemm_tf32_kernel<true, true><<<dim3(HH / 64, MM / 128), 256>>>(
        norm, ff_w, ff_b, out, out, MM, HH, HH);
}

// round 3
// speedup vs baseline: 3.3867x; 2.2782x over previous
#include <cuda_runtime.h>
#include <math.h>

// Problem constants
#define BB   32
#define LL   400
#define HH   512
#define NHH  8
#define DHH  64
#define KW   7
#define NCC  4
#define MM   (BB * LL)      // 12800 tokens
#define H3   (3 * HH)       // 1536

// ---------------------------------------------------------------------------
// Scratch
// ---------------------------------------------------------------------------
__device__ float g_norm  [MM * HH];
__device__ float g_dwout [MM * HH];
__device__ float g_qkv   [MM * H3];
__device__ float g_attout[MM * HH];

// ---------------------------------------------------------------------------
// out = x + positional encoding
// ---------------------------------------------------------------------------
__global__ void add_pe_kernel(const float* __restrict__ x, float* __restrict__ out) {
    int idx = blockIdx.x * blockDim.x + threadIdx.x;
    if (idx >= MM * HH) return;
    int h = idx & (HH - 1);
    int l = (idx / HH) % LL;
    float freq = expf(-(float)(h & ~1) * (9.210340371976184f / (float)HH));
    float a = (float)l * freq;
    float pe = (h & 1) ? cosf(a) : sinf(a);
    out[idx] = x[idx] + pe;
}

// ---------------------------------------------------------------------------
// LayerNorm over last dim (H=512). One block per row, 128 threads, float4.
// ---------------------------------------------------------------------------
__global__ void ln_kernel(const float* __restrict__ in, float* __restrict__ out,
                          const float* __restrict__ gw, const float* __restrict__ gb) {
    int row = blockIdx.x;
    int t   = threadIdx.x;  // 128
    const float4* p = (const float4*)(in + (size_t)row * HH);
    float4 v = p[t];

    __shared__ float sh[4];

    float s = v.x + v.y + v.z + v.w;
    #pragma unroll
    for (int o = 16; o > 0; o >>= 1) s += __shfl_down_sync(0xffffffffu, s, o);
    if ((t & 31) == 0) sh[t >> 5] = s;
    __syncthreads();
    float mean = (sh[0] + sh[1] + sh[2] + sh[3]) * (1.0f / HH);
    __syncthreads();

    float dx = v.x - mean, dy = v.y - mean, dz = v.z - mean, dw = v.w - mean;
    float q = dx * dx + dy * dy + dz * dz + dw * dw;
    #pragma unroll
    for (int o = 16; o > 0; o >>= 1) q += __shfl_down_sync(0xffffffffu, q, o);
    if ((t & 31) == 0) sh[t >> 5] = q;
    __syncthreads();
    float var  = (sh[0] + sh[1] + sh[2] + sh[3]) * (1.0f / HH);
    float rstd = rsqrtf(var + 1e-5f);

    float4 g4 = ((const float4*)gw)[t];
    float4 b4 = ((const float4*)gb)[t];
    float4 o4;
    o4.x = dx * rstd * g4.x + b4.x;
    o4.y = dy * rstd * g4.y + b4.y;
    o4.z = dz * rstd * g4.z + b4.z;
    o4.w = dw * rstd * g4.w + b4.w;
    ((float4*)(out + (size_t)row * HH))[t] = o4;
}

// ---------------------------------------------------------------------------
// Depthwise conv K=7, pad 3, over (B,L,C) layout.
// ---------------------------------------------------------------------------
__global__ void dwconv_kernel(const float* __restrict__ norm, float* __restrict__ outb,
                              const float* __restrict__ w, const float* __restrict__ bias) {
    int idx = blockIdx.x * blockDim.x + threadIdx.x;
    if (idx >= MM * HH) return;
    int c = idx & (HH - 1);
    int l = (idx / HH) % LL;
    int b = idx / (HH * LL);
    const float* wr = w + c * KW;
    float acc = bias[c];
    #pragma unroll
    for (int k = 0; k < KW; k++) {
        int ll = l + k - 3;
        if (ll >= 0 && ll < LL)
            acc += norm[((size_t)b * LL + ll) * HH + c] * wr[k];
    }
    outb[idx] = acc;
}

// ---------------------------------------------------------------------------
// tf32 helpers
// ---------------------------------------------------------------------------
__device__ __forceinline__ unsigned f2tf32(float x) {
    unsigned r;
    asm("cvt.rna.tf32.f32 %0, %1;" : "=r"(r) : "f"(x));
    return r;
}

__device__ __forceinline__ void mma_tf32(float* d, const unsigned* a, const unsigned* b) {
    asm volatile(
        "mma.sync.aligned.m16n8k8.row.col.f32.tf32.tf32.f32 "
        "{%0,%1,%2,%3}, {%4,%5,%6,%7}, {%8,%9}, {%0,%1,%2,%3};\n"
        : "+f"(d[0]), "+f"(d[1]), "+f"(d[2]), "+f"(d[3])
        : "r"(a[0]), "r"(a[1]), "r"(a[2]), "r"(a[3]), "r"(b[0]), "r"(b[1]));
}

// ---------------------------------------------------------------------------
// tf32 tensor-core GEMM (BM=128, BN=64, BK=16, 256 thr, warp tile 32x32)
// ---------------------------------------------------------------------------
template <bool RELU, bool RES>
__global__ void __launch_bounds__(256)
gemm_tf32_kernel(const float* __restrict__ A, const float* __restrict__ W,
                 const float* __restrict__ bias, const float* __restrict__ R,
                 float* __restrict__ C, int Md, int Nd, int Kd) {
    __shared__ unsigned As[128][20];
    __shared__ unsigned Ws[64][20];

    int tid  = threadIdx.x;
    int m0   = blockIdx.y * 128;
    int n0   = blockIdx.x * 64;
    int warp = tid >> 5;
    int lane = tid & 31;
    int wm   = (warp >> 1) * 32;
    int wn   = (warp & 1) * 32;
    int lg   = lane >> 2;
    int lq   = lane & 3;

    int lrow = tid >> 2;
    int lk   = (tid & 3) * 4;

    float acc[2][4][4];
    #pragma unroll
    for (int i = 0; i < 2; i++)
        #pragma unroll
        for (int j = 0; j < 4; j++)
            #pragma unroll
            for (int r = 0; r < 4; r++) acc[i][j][r] = 0.0f;

    for (int k0 = 0; k0 < Kd; k0 += 16) {
        float4 av0 = *(const float4*)&A[(size_t)(m0 + lrow)      * Kd + k0 + lk];
        float4 av1 = *(const float4*)&A[(size_t)(m0 + 64 + lrow) * Kd + k0 + lk];
        float4 wv  = *(const float4*)&W[(size_t)(n0 + lrow)      * Kd + k0 + lk];
        As[lrow][lk + 0] = f2tf32(av0.x); As[lrow][lk + 1] = f2tf32(av0.y);
        As[lrow][lk + 2] = f2tf32(av0.z); As[lrow][lk + 3] = f2tf32(av0.w);
        As[64 + lrow][lk + 0] = f2tf32(av1.x); As[64 + lrow][lk + 1] = f2tf32(av1.y);
        As[64 + lrow][lk + 2] = f2tf32(av1.z); As[64 + lrow][lk + 3] = f2tf32(av1.w);
        Ws[lrow][lk + 0] = f2tf32(wv.x); Ws[lrow][lk + 1] = f2tf32(wv.y);
        Ws[lrow][lk + 2] = f2tf32(wv.z); Ws[lrow][lk + 3] = f2tf32(wv.w);
        __syncthreads();

        #pragma unroll
        for (int ks = 0; ks < 2; ks++) {
            int kb = ks * 8;
            unsigned af[2][4], bf[4][2];
            #pragma unroll
            for (int mt = 0; mt < 2; mt++) {
                int mr = wm + mt * 16 + lg;
                af[mt][0] = As[mr][kb + lq];
                af[mt][1] = As[mr + 8][kb + lq];
                af[mt][2] = As[mr][kb + lq + 4];
                af[mt][3] = As[mr + 8][kb + lq + 4];
            }
            #pragma unroll
            for (int nt = 0; nt < 4; nt++) {
                int nr = wn + nt * 8 + lg;
                bf[nt][0] = Ws[nr][kb + lq];
                bf[nt][1] = Ws[nr][kb + lq + 4];
            }
            #pragma unroll
            for (int mt = 0; mt < 2; mt++)
                #pragma unroll
                for (int nt = 0; nt < 4; nt++)
                    mma_tf32(acc[mt][nt], af[mt], bf[nt]);
        }
        __syncthreads();
    }

    #pragma unroll
    for (int mt = 0; mt < 2; mt++) {
        #pragma unroll
        for (int half = 0; half < 2; half++) {
            int m = m0 + wm + mt * 16 + lg + half * 8;
            #pragma unroll
            for (int nt = 0; nt < 4; nt++) {
                int n = n0 + wn + nt * 8 + 2 * lq;
                float v0 = acc[mt][nt][half * 2 + 0] + bias[n];
                float v1 = acc[mt][nt][half * 2 + 1] + bias[n + 1];
                if (RELU) { v0 = fmaxf(v0, 0.0f); v1 = fmaxf(v1, 0.0f); }
                if (RES)  { v0 += R[(size_t)m * Nd + n]; v1 += R[(size_t)m * Nd + n + 1]; }
                *(float2*)&C[(size_t)m * Nd + n] = make_float2(v0, v1);
            }
        }
    }
}

// ---------------------------------------------------------------------------
// Fused flash attention (tf32 MMA, online softmax, no S buffer).
// Block = (b*NH+h, q-tile of 64). 128 threads = 4 warps x 16 q-rows.
// K/V tiles of 64. Smem: Qs[64x68], KPs[64x68] (K, reused for P), Vs[64x72].
// ---------------------------------------------------------------------------
#define QS_STRIDE 68
#define VS_STRIDE 72
#define FLASH_SMEM ((64 * QS_STRIDE * 2 + 64 * VS_STRIDE) * 4)

__global__ void __launch_bounds__(128)
flash_kernel(const float* __restrict__ qkv, const int* __restrict__ mask,
             float* __restrict__ attout) {
    extern __shared__ unsigned fsm[];
    unsigned* Qs  = fsm;                       // [64][68]
    unsigned* KPs = fsm + 64 * QS_STRIDE;      // [64][68]
    unsigned* Vs  = fsm + 2 * 64 * QS_STRIDE;  // [64][72]
    __shared__ int msk[64];

    int bh = blockIdx.x;
    int b  = bh >> 3;
    int h  = bh & 7;
    int q0 = blockIdx.y * 64;

    int tid  = threadIdx.x;
    int warp = tid >> 5;
    int lane = tid & 31;
    int wr   = warp * 16;
    int lg   = lane >> 2;
    int lq   = lane & 3;

    // Load Q tile (scaled by 1/sqrt(d)=0.125), tf32, clamped rows
    for (int i = tid; i < 64 * 16; i += 128) {
        int r  = i >> 4;
        int c4 = (i & 15) * 4;
        int qr = q0 + r; if (qr > LL - 1) qr = LL - 1;
        float4 v = *(const float4*)&qkv[((size_t)(b * LL + qr)) * H3 + h * DHH + c4];
        Qs[r * QS_STRIDE + c4 + 0] = f2tf32(v.x * 0.125f);
        Qs[r * QS_STRIDE + c4 + 1] = f2tf32(v.y * 0.125f);
        Qs[r * QS_STRIDE + c4 + 2] = f2tf32(v.z * 0.125f);
        Qs[r * QS_STRIDE + c4 + 3] = f2tf32(v.w * 0.125f);
    }

    float oacc[8][4];
    #pragma unroll
    for (int nt = 0; nt < 8; nt++)
        #pragma unroll
        for (int r = 0; r < 4; r++) oacc[nt][r] = 0.0f;
    float m0 = -1e30f, m1 = -1e30f, l0 = 0.0f, l1 = 0.0f;

    for (int kt = 0; kt < LL; kt += 64) {
        __syncthreads();  // protect KPs/Vs from previous iteration readers

        // Load K, V tiles (tf32), mask
        for (int i = tid; i < 64 * 16; i += 128) {
            int r  = i >> 4;
            int c4 = (i & 15) * 4;
            int kr = kt + r; if (kr > LL - 1) kr = LL - 1;
            const float* base = &qkv[((size_t)(b * LL + kr)) * H3 + h * DHH + c4];
            float4 kv = *(const float4*)(base + HH);
            float4 vv = *(const float4*)(base + 2 * HH);
            KPs[r * QS_STRIDE + c4 + 0] = f2tf32(kv.x);
            KPs[r * QS_STRIDE + c4 + 1] = f2tf32(kv.y);
            KPs[r * QS_STRIDE + c4 + 2] = f2tf32(kv.z);
            KPs[r * QS_STRIDE + c4 + 3] = f2tf32(kv.w);
            Vs[r * VS_STRIDE + c4 + 0] = f2tf32(vv.x);
            Vs[r * VS_STRIDE + c4 + 1] = f2tf32(vv.y);
            Vs[r * VS_STRIDE + c4 + 2] = f2tf32(vv.z);
            Vs[r * VS_STRIDE + c4 + 3] = f2tf32(vv.w);
        }
        if (tid < 64) msk[tid] = (kt + tid < LL) ? mask[b * LL + kt + tid] : 0;
        __syncthreads();

        // S = Q @ K^T  (16 rows per warp x 64 keys)
        float sacc[8][4];
        #pragma unroll
        for (int nt = 0; nt < 8; nt++)
            #pragma unroll
            for (int r = 0; r < 4; r++) sacc[nt][r] = 0.0f;

        #pragma unroll
        for (int ks = 0; ks < 8; ks++) {
            int kb = ks * 8;
            unsigned af[4];
            af[0] = Qs[(wr + lg)     * QS_STRIDE + kb + lq];
            af[1] = Qs[(wr + lg + 8) * QS_STRIDE + kb + lq];
            af[2] = Qs[(wr + lg)     * QS_STRIDE + kb + lq + 4];
            af[3] = Qs[(wr + lg + 8) * QS_STRIDE + kb + lq + 4];
            #pragma unroll
            for (int nt = 0; nt < 8; nt++) {
                unsigned bf[2];
                bf[0] = KPs[(nt * 8 + lg) * QS_STRIDE + kb + lq];
                bf[1] = KPs[(nt * 8 + lg) * QS_STRIDE + kb + lq + 4];
                mma_tf32(sacc[nt], af, bf);
            }
        }

        // Mask + row max
        float rmax0 = -1e30f, rmax1 = -1e30f;
        #pragma unroll
        for (int nt = 0; nt < 8; nt++) {
            #pragma unroll
            for (int j = 0; j < 2; j++) {
                int kl = nt * 8 + 2 * lq + j;
                bool ok = (kt + kl < LL) && (msk[kl] > 0);
                if (!ok) { sacc[nt][j] = -1e30f; sacc[nt][2 + j] = -1e30f; }
                rmax0 = fmaxf(rmax0, sacc[nt][j]);
                rmax1 = fmaxf(rmax1, sacc[nt][2 + j]);
            }
        }
        #pragma unroll
        for (int o = 1; o <= 2; o <<= 1) {
            rmax0 = fmaxf(rmax0, __shfl_xor_sync(0xffffffffu, rmax0, o));
            rmax1 = fmaxf(rmax1, __shfl_xor_sync(0xffffffffu, rmax1, o));
        }

        float m0n = fmaxf(m0, rmax0);
        float m1n = fmaxf(m1, rmax1);
        float alpha0 = __expf(m0 - m0n);
        float alpha1 = __expf(m1 - m1n);
        m0 = m0n; m1 = m1n;

        float rs0 = 0.0f, rs1 = 0.0f;
        #pragma unroll
        for (int nt = 0; nt < 8; nt++) {
            #pragma unroll
            for (int j = 0; j < 2; j++) {
                float p0 = __expf(sacc[nt][j] - m0);
                float p1 = __expf(sacc[nt][2 + j] - m1);
                sacc[nt][j] = p0;     rs0 += p0;
                sacc[nt][2 + j] = p1; rs1 += p1;
            }
        }
        #pragma unroll
        for (int o = 1; o <= 2; o <<= 1) {
            rs0 += __shfl_xor_sync(0xffffffffu, rs0, o);
            rs1 += __shfl_xor_sync(0xffffffffu, rs1, o);
        }
        l0 = l0 * alpha0 + rs0;
        l1 = l1 * alpha1 + rs1;

        #pragma unroll
        for (int nt = 0; nt < 8; nt++) {
            oacc[nt][0] *= alpha0; oacc[nt][1] *= alpha0;
            oacc[nt][2] *= alpha1; oacc[nt][3] *= alpha1;
        }

        // All warps must finish reading K before P overwrites it
        __syncthreads();

        // Store P (tf32) into KPs rows owned by this warp
        #pragma unroll
        for (int nt = 0; nt < 8; nt++) {
            int c = nt * 8 + 2 * lq;
            KPs[(wr + lg)     * QS_STRIDE + c]     = f2tf32(sacc[nt][0]);
            KPs[(wr + lg)     * QS_STRIDE + c + 1] = f2tf32(sacc[nt][1]);
            KPs[(wr + lg + 8) * QS_STRIDE + c]     = f2tf32(sacc[nt][2]);
            KPs[(wr + lg + 8) * QS_STRIDE + c + 1] = f2tf32(sacc[nt][3]);
        }
        __syncwarp();

        // O += P @ V
        #pragma unroll
        for (int ks = 0; ks < 8; ks++) {
            int kb = ks * 8;
            unsigned af[4];
            af[0] = KPs[(wr + lg)     * QS_STRIDE + kb + lq];
            af[1] = KPs[(wr + lg + 8) * QS_STRIDE + kb + lq];
            af[2] = KPs[(wr + lg)     * QS_STRIDE + kb + lq + 4];
            af[3] = KPs[(wr + lg + 8) * QS_STRIDE + kb + lq + 4];
            #pragma unroll
            for (int nt = 0; nt < 8; nt++) {
                unsigned bf[2];
                bf[0] = Vs[(kb + lq)     * VS_STRIDE + nt * 8 + lg];
                bf[1] = Vs[(kb + lq + 4) * VS_STRIDE + nt * 8 + lg];
                mma_tf32(oacc[nt], af, bf);
            }
        }
    }

    // Epilogue: divide by l, store
    float inv0 = 1.0f / fmaxf(l0, 1e-30f);
    float inv1 = 1.0f / fmaxf(l1, 1e-30f);
    int r0 = q0 + wr + lg;
    int r1 = r0 + 8;
    #pragma unroll
    for (int nt = 0; nt < 8; nt++) {
        int c = nt * 8 + 2 * lq;
        if (r0 < LL)
            *(float2*)&attout[((size_t)(b * LL + r0)) * HH + h * DHH + c] =
                make_float2(oacc[nt][0] * inv0, oacc[nt][1] * inv0);
        if (r1 < LL)
            *(float2*)&attout[((size_t)(b * LL + r1)) * HH + h * DHH + c] =
                make_float2(oacc[nt][2] * inv1, oacc[nt][3] * inv1);
    }
}

// ---------------------------------------------------------------------------
// Launch
// ---------------------------------------------------------------------------
extern "C" void kernel_launch(void* const* d_in, const int* in_sizes, int n_in,
                              void* d_out, int out_size) {
    const float* x         = (const float*)d_in[0];
    const int*   mask      = (const int*)  d_in[1];
    const float* conv_ln_g = (const float*)d_in[2];
    const float* conv_ln_b = (const float*)d_in[3];
    const float* dw_w      = (const float*)d_in[4];
    const float* dw_b      = (const float*)d_in[5];
    const float* pw_w      = (const float*)d_in[6];
    const float* pw_b      = (const float*)d_in[7];
    const float* att_ln_g  = (const float*)d_in[8];
    const float* att_ln_b  = (const float*)d_in[9];
    const float* qkv_w     = (const float*)d_in[10];
    const float* qkv_b     = (const float*)d_in[11];
    const float* out_w     = (const float*)d_in[12];
    const float* out_b     = (const float*)d_in[13];
    const float* ff_ln_g   = (const float*)d_in[14];
    const float* ff_ln_b   = (const float*)d_in[15];
    const float* ff_w      = (const float*)d_in[16];
    const float* ff_b      = (const float*)d_in[17];
    float* out = (float*)d_out;

    float *norm, *dwout, *qkv, *attout;
    cudaGetSymbolAddress((void**)&norm,   g_norm);
    cudaGetSymbolAddress((void**)&dwout,  g_dwout);
    cudaGetSymbolAddress((void**)&qkv,    g_qkv);
    cudaGetSymbolAddress((void**)&attout, g_attout);

    cudaFuncSetAttribute(flash_kernel,
                         cudaFuncAttributeMaxDynamicSharedMemorySize, FLASH_SMEM);

    const int elems = MM * HH;

    add_pe_kernel<<<(elems + 255) / 256, 256>>>(x, out);

    for (int i = 0; i < NCC; i++) {
        ln_kernel<<<MM, 128>>>(out, norm, conv_ln_g + i * HH, conv_ln_b + i * HH);
        dwconv_kernel<<<(elems + 255) / 256, 256>>>(norm, dwout,
                                                    dw_w + i * HH * KW, dw_b + i * HH);
        gemm_tf32_kernel<true, true><<<dim3(HH / 64, MM / 128), 256>>>(
            dwout, pw_w + (size_t)i * HH * HH, pw_b + i * HH, out, out, MM, HH, HH);
    }

    ln_kernel<<<MM, 128>>>(out, norm, att_ln_g, att_ln_b);
    gemm_tf32_kernel<false, false><<<dim3(H3 / 64, MM / 128), 256>>>(
        norm, qkv_w, qkv_b, nullptr, qkv, MM, H3, HH);

    flash_kernel<<<dim3(BB * NHH, (LL + 63) / 64), 128, FLASH_SMEM>>>(qkv, mask, attout);

    gemm_tf32_kernel<false, true><<<dim3(HH / 64, MM / 128), 256>>>(
        attout, out_w, out_b, out, out, MM, HH, HH);

    ln_kernel<<<MM, 128>>>(out, norm, ff_ln_g, ff_ln_b);
    gemm_tf32_kernel<true, true><<<dim3(HH / 64, MM / 128), 256>>>(
        norm, ff_w, ff_b, out, out, MM, HH, HH);
}

// round 4
// speedup vs baseline: 4.1615x; 1.2288x over previous
#include <cuda_runtime.h>
#include <math.h>

// Problem constants
#define BB   32
#define LL   400
#define HH   512
#define NHH  8
#define DHH  64
#define KW   7
#define NCC  4
#define MM   (BB * LL)      // 12800 tokens
#define H3   (3 * HH)       // 1536

// ---------------------------------------------------------------------------
// Scratch
// ---------------------------------------------------------------------------
__device__ float g_norm  [MM * HH];
__device__ float g_dwout [MM * HH];
__device__ float g_qkv   [MM * H3];
__device__ float g_attout[MM * HH];

// ---------------------------------------------------------------------------
// out = x + positional encoding
// ---------------------------------------------------------------------------
__global__ void add_pe_kernel(const float* __restrict__ x, float* __restrict__ out) {
    int idx = blockIdx.x * blockDim.x + threadIdx.x;
    if (idx >= MM * HH) return;
    int h = idx & (HH - 1);
    int l = (idx / HH) % LL;
    float freq = expf(-(float)(h & ~1) * (9.210340371976184f / (float)HH));
    float a = (float)l * freq;
    float pe = (h & 1) ? cosf(a) : sinf(a);
    out[idx] = x[idx] + pe;
}

// ---------------------------------------------------------------------------
// LayerNorm over last dim (H=512). One block per row, 128 threads, float4.
// ---------------------------------------------------------------------------
__global__ void ln_kernel(const float* __restrict__ in, float* __restrict__ out,
                          const float* __restrict__ gw, const float* __restrict__ gb) {
    int row = blockIdx.x;
    int t   = threadIdx.x;  // 128
    const float4* p = (const float4*)(in + (size_t)row * HH);
    float4 v = p[t];

    __shared__ float sh[4];

    float s = v.x + v.y + v.z + v.w;
    #pragma unroll
    for (int o = 16; o > 0; o >>= 1) s += __shfl_down_sync(0xffffffffu, s, o);
    if ((t & 31) == 0) sh[t >> 5] = s;
    __syncthreads();
    float mean = (sh[0] + sh[1] + sh[2] + sh[3]) * (1.0f / HH);
    __syncthreads();

    float dx = v.x - mean, dy = v.y - mean, dz = v.z - mean, dw = v.w - mean;
    float q = dx * dx + dy * dy + dz * dz + dw * dw;
    #pragma unroll
    for (int o = 16; o > 0; o >>= 1) q += __shfl_down_sync(0xffffffffu, q, o);
    if ((t & 31) == 0) sh[t >> 5] = q;
    __syncthreads();
    float var  = (sh[0] + sh[1] + sh[2] + sh[3]) * (1.0f / HH);
    float rstd = rsqrtf(var + 1e-5f);

    float4 g4 = ((const float4*)gw)[t];
    float4 b4 = ((const float4*)gb)[t];
    float4 o4;
    o4.x = dx * rstd * g4.x + b4.x;
    o4.y = dy * rstd * g4.y + b4.y;
    o4.z = dz * rstd * g4.z + b4.z;
    o4.w = dw * rstd * g4.w + b4.w;
    ((float4*)(out + (size_t)row * HH))[t] = o4;
}

// ---------------------------------------------------------------------------
// Depthwise conv K=7, pad 3, over (B,L,C) layout.
// ---------------------------------------------------------------------------
__global__ void dwconv_kernel(const float* __restrict__ norm, float* __restrict__ outb,
                              const float* __restrict__ w, const float* __restrict__ bias) {
    int idx = blockIdx.x * blockDim.x + threadIdx.x;
    if (idx >= MM * HH) return;
    int c = idx & (HH - 1);
    int l = (idx / HH) % LL;
    int b = idx / (HH * LL);
    const float* wr = w + c * KW;
    float acc = bias[c];
    #pragma unroll
    for (int k = 0; k < KW; k++) {
        int ll = l + k - 3;
        if (ll >= 0 && ll < LL)
            acc += norm[((size_t)b * LL + ll) * HH + c] * wr[k];
    }
    outb[idx] = acc;
}

// ---------------------------------------------------------------------------
// tf32 helpers
// ---------------------------------------------------------------------------
__device__ __forceinline__ unsigned f2tf32(float x) {
    unsigned r;
    asm("cvt.rna.tf32.f32 %0, %1;" : "=r"(r) : "f"(x));
    return r;
}

__device__ __forceinline__ void mma_tf32(float* d, const unsigned* a, const unsigned* b) {
    asm volatile(
        "mma.sync.aligned.m16n8k8.row.col.f32.tf32.tf32.f32 "
        "{%0,%1,%2,%3}, {%4,%5,%6,%7}, {%8,%9}, {%0,%1,%2,%3};\n"
        : "+f"(d[0]), "+f"(d[1]), "+f"(d[2]), "+f"(d[3])
        : "r"(a[0]), "r"(a[1]), "r"(a[2]), "r"(a[3]), "r"(b[0]), "r"(b[1]));
}

__device__ __forceinline__ void cp_async16(void* smem_dst, const void* gsrc) {
    unsigned sa = (unsigned)__cvta_generic_to_shared(smem_dst);
    asm volatile("cp.async.cg.shared.global [%0], [%1], 16;\n" :: "r"(sa), "l"(gsrc));
}

// ---------------------------------------------------------------------------
// tf32 tensor-core GEMM, double-buffered cp.async.
// BM=128, BN=128, BK=16, 256 threads (8 warps, 2x4), warp tile 64x32.
// C[m,n] = act( sum_k A[m,k]*W[n,k] + bias[n] ) (+ R[m,n])
// M%128==0, N%128==0, K%16==0 at all call sites.
// ---------------------------------------------------------------------------
template <bool RELU, bool RES>
__global__ void __launch_bounds__(256)
gemm_tf32_kernel(const float* __restrict__ A, const float* __restrict__ W,
                 const float* __restrict__ bias, const float* __restrict__ R,
                 float* __restrict__ C, int Md, int Nd, int Kd) {
    __shared__ float As[2][128][20];
    __shared__ float Bs[2][128][20];

    int tid  = threadIdx.x;
    int m0   = blockIdx.y * 128;
    int n0   = blockIdx.x * 128;
    int warp = tid >> 5;
    int lane = tid & 31;
    int wm   = (warp >> 2) * 64;  // 0,64
    int wn   = (warp & 3) * 32;   // 0,32,64,96
    int lg   = lane >> 2;         // 0..7
    int lq   = lane & 3;          // 0..3

    int lrow = tid >> 2;          // 0..63
    int lk   = (tid & 3) * 4;     // 0,4,8,12

    const float* Ar0 = &A[(size_t)(m0 + lrow)      * Kd + lk];
    const float* Ar1 = &A[(size_t)(m0 + 64 + lrow) * Kd + lk];
    const float* Wr0 = &W[(size_t)(n0 + lrow)      * Kd + lk];
    const float* Wr1 = &W[(size_t)(n0 + 64 + lrow) * Kd + lk];

    float acc[4][4][4];
    #pragma unroll
    for (int i = 0; i < 4; i++)
        #pragma unroll
        for (int j = 0; j < 4; j++)
            #pragma unroll
            for (int r = 0; r < 4; r++) acc[i][j][r] = 0.0f;

    // Prologue: stage 0
    cp_async16(&As[0][lrow][lk],      Ar0);
    cp_async16(&As[0][64 + lrow][lk], Ar1);
    cp_async16(&Bs[0][lrow][lk],      Wr0);
    cp_async16(&Bs[0][64 + lrow][lk], Wr1);
    asm volatile("cp.async.commit_group;\n");

    int nit = Kd >> 4;
    for (int it = 0; it < nit; it++) {
        int cur = it & 1;
        if (it + 1 < nit) {
            int nxt = cur ^ 1;
            int ko  = (it + 1) << 4;
            cp_async16(&As[nxt][lrow][lk],      Ar0 + ko);
            cp_async16(&As[nxt][64 + lrow][lk], Ar1 + ko);
            cp_async16(&Bs[nxt][lrow][lk],      Wr0 + ko);
            cp_async16(&Bs[nxt][64 + lrow][lk], Wr1 + ko);
            asm volatile("cp.async.commit_group;\n");
            asm volatile("cp.async.wait_group 1;\n");
        } else {
            asm volatile("cp.async.wait_group 0;\n");
        }
        __syncthreads();

        #pragma unroll
        for (int ks = 0; ks < 2; ks++) {
            int kb = ks * 8;
            unsigned af[4][4], bf[4][2];
            #pragma unroll
            for (int mt = 0; mt < 4; mt++) {
                int mr = wm + mt * 16 + lg;
                af[mt][0] = f2tf32(As[cur][mr][kb + lq]);
                af[mt][1] = f2tf32(As[cur][mr + 8][kb + lq]);
                af[mt][2] = f2tf32(As[cur][mr][kb + lq + 4]);
                af[mt][3] = f2tf32(As[cur][mr + 8][kb + lq + 4]);
            }
            #pragma unroll
            for (int nt = 0; nt < 4; nt++) {
                int nr = wn + nt * 8 + lg;
                bf[nt][0] = f2tf32(Bs[cur][nr][kb + lq]);
                bf[nt][1] = f2tf32(Bs[cur][nr][kb + lq + 4]);
            }
            #pragma unroll
            for (int mt = 0; mt < 4; mt++)
                #pragma unroll
                for (int nt = 0; nt < 4; nt++)
                    mma_tf32(acc[mt][nt], af[mt], bf[nt]);
        }
        __syncthreads();
    }

    // Epilogue
    #pragma unroll
    for (int mt = 0; mt < 4; mt++) {
        #pragma unroll
        for (int half = 0; half < 2; half++) {
            int m = m0 + wm + mt * 16 + lg + half * 8;
            #pragma unroll
            for (int nt = 0; nt < 4; nt++) {
                int n = n0 + wn + nt * 8 + 2 * lq;
                float v0 = acc[mt][nt][half * 2 + 0] + bias[n];
                float v1 = acc[mt][nt][half * 2 + 1] + bias[n + 1];
                if (RELU) { v0 = fmaxf(v0, 0.0f); v1 = fmaxf(v1, 0.0f); }
                if (RES)  { v0 += R[(size_t)m * Nd + n]; v1 += R[(size_t)m * Nd + n + 1]; }
                *(float2*)&C[(size_t)m * Nd + n] = make_float2(v0, v1);
            }
        }
    }
}

// ---------------------------------------------------------------------------
// Fused flash attention (tf32 MMA, online softmax, no S buffer).
// Block = (b*NH+h, q-tile of 64). 128 threads = 4 warps x 16 q-rows.
// ---------------------------------------------------------------------------
#define QS_STRIDE 68
#define VS_STRIDE 72
#define FLASH_SMEM ((64 * QS_STRIDE * 2 + 64 * VS_STRIDE) * 4)

__global__ void __launch_bounds__(128)
flash_kernel(const float* __restrict__ qkv, const int* __restrict__ mask,
             float* __restrict__ attout) {
    extern __shared__ unsigned fsm[];
    unsigned* Qs  = fsm;
    unsigned* KPs = fsm + 64 * QS_STRIDE;
    unsigned* Vs  = fsm + 2 * 64 * QS_STRIDE;
    __shared__ int msk[64];

    int bh = blockIdx.x;
    int b  = bh >> 3;
    int h  = bh & 7;
    int q0 = blockIdx.y * 64;

    int tid  = threadIdx.x;
    int warp = tid >> 5;
    int lane = tid & 31;
    int wr   = warp * 16;
    int lg   = lane >> 2;
    int lq   = lane & 3;

    for (int i = tid; i < 64 * 16; i += 128) {
        int r  = i >> 4;
        int c4 = (i & 15) * 4;
        int qr = q0 + r; if (qr > LL - 1) qr = LL - 1;
        float4 v = *(const float4*)&qkv[((size_t)(b * LL + qr)) * H3 + h * DHH + c4];
        Qs[r * QS_STRIDE + c4 + 0] = f2tf32(v.x * 0.125f);
        Qs[r * QS_STRIDE + c4 + 1] = f2tf32(v.y * 0.125f);
        Qs[r * QS_STRIDE + c4 + 2] = f2tf32(v.z * 0.125f);
        Qs[r * QS_STRIDE + c4 + 3] = f2tf32(v.w * 0.125f);
    }

    float oacc[8][4];
    #pragma unroll
    for (int nt = 0; nt < 8; nt++)
        #pragma unroll
        for (int r = 0; r < 4; r++) oacc[nt][r] = 0.0f;
    float m0 = -1e30f, m1 = -1e30f, l0 = 0.0f, l1 = 0.0f;

    for (int kt = 0; kt < LL; kt += 64) {
        __syncthreads();

        for (int i = tid; i < 64 * 16; i += 128) {
            int r  = i >> 4;
            int c4 = (i & 15) * 4;
            int kr = kt + r; if (kr > LL - 1) kr = LL - 1;
            const float* base = &qkv[((size_t)(b * LL + kr)) * H3 + h * DHH + c4];
            float4 kv = *(const float4*)(base + HH);
            float4 vv = *(const float4*)(base + 2 * HH);
            KPs[r * QS_STRIDE + c4 + 0] = f2tf32(kv.x);
            KPs[r * QS_STRIDE + c4 + 1] = f2tf32(kv.y);
            KPs[r * QS_STRIDE + c4 + 2] = f2tf32(kv.z);
            KPs[r * QS_STRIDE + c4 + 3] = f2tf32(kv.w);
            Vs[r * VS_STRIDE + c4 + 0] = f2tf32(vv.x);
            Vs[r * VS_STRIDE + c4 + 1] = f2tf32(vv.y);
            Vs[r * VS_STRIDE + c4 + 2] = f2tf32(vv.z);
            Vs[r * VS_STRIDE + c4 + 3] = f2tf32(vv.w);
        }
        if (tid < 64) msk[tid] = (kt + tid < LL) ? mask[b * LL + kt + tid] : 0;
        __syncthreads();

        float sacc[8][4];
        #pragma unroll
        for (int nt = 0; nt < 8; nt++)
            #pragma unroll
            for (int r = 0; r < 4; r++) sacc[nt][r] = 0.0f;

        #pragma unroll
        for (int ks = 0; ks < 8; ks++) {
            int kb = ks * 8;
            unsigned af[4];
            af[0] = Qs[(wr + lg)     * QS_STRIDE + kb + lq];
            af[1] = Qs[(wr + lg + 8) * QS_STRIDE + kb + lq];
            af[2] = Qs[(wr + lg)     * QS_STRIDE + kb + lq + 4];
            af[3] = Qs[(wr + lg + 8) * QS_STRIDE + kb + lq + 4];
            #pragma unroll
            for (int nt = 0; nt < 8; nt++) {
                unsigned bf[2];
                bf[0] = KPs[(nt * 8 + lg) * QS_STRIDE + kb + lq];
                bf[1] = KPs[(nt * 8 + lg) * QS_STRIDE + kb + lq + 4];
                mma_tf32(sacc[nt], af, bf);
            }
        }

        float rmax0 = -1e30f, rmax1 = -1e30f;
        #pragma unroll
        for (int nt = 0; nt < 8; nt++) {
            #pragma unroll
            for (int j = 0; j < 2; j++) {
                int kl = nt * 8 + 2 * lq + j;
                bool ok = (kt + kl < LL) && (msk[kl] > 0);
                if (!ok) { sacc[nt][j] = -1e30f; sacc[nt][2 + j] = -1e30f; }
                rmax0 = fmaxf(rmax0, sacc[nt][j]);
                rmax1 = fmaxf(rmax1, sacc[nt][2 + j]);
            }
        }
        #pragma unroll
        for (int o = 1; o <= 2; o <<= 1) {
            rmax0 = fmaxf(rmax0, __shfl_xor_sync(0xffffffffu, rmax0, o));
            rmax1 = fmaxf(rmax1, __shfl_xor_sync(0xffffffffu, rmax1, o));
        }

        float m0n = fmaxf(m0, rmax0);
        float m1n = fmaxf(m1, rmax1);
        float alpha0 = __expf(m0 - m0n);
        float alpha1 = __expf(m1 - m1n);
        m0 = m0n; m1 = m1n;

        float rs0 = 0.0f, rs1 = 0.0f;
        #pragma unroll
        for (int nt = 0; nt < 8; nt++) {
            #pragma unroll
            for (int j = 0; j < 2; j++) {
                float p0 = __expf(sacc[nt][j] - m0);
                float p1 = __expf(sacc[nt][2 + j] - m1);
                sacc[nt][j] = p0;     rs0 += p0;
                sacc[nt][2 + j] = p1; rs1 += p1;
            }
        }
        #pragma unroll
        for (int o = 1; o <= 2; o <<= 1) {
            rs0 += __shfl_xor_sync(0xffffffffu, rs0, o);
            rs1 += __shfl_xor_sync(0xffffffffu, rs1, o);
        }
        l0 = l0 * alpha0 + rs0;
        l1 = l1 * alpha1 + rs1;

        #pragma unroll
        for (int nt = 0; nt < 8; nt++) {
            oacc[nt][0] *= alpha0; oacc[nt][1] *= alpha0;
            oacc[nt][2] *= alpha1; oacc[nt][3] *= alpha1;
        }

        __syncthreads();

        #pragma unroll
        for (int nt = 0; nt < 8; nt++) {
            int c = nt * 8 + 2 * lq;
            KPs[(wr + lg)     * QS_STRIDE + c]     = f2tf32(sacc[nt][0]);
            KPs[(wr + lg)     * QS_STRIDE + c + 1] = f2tf32(sacc[nt][1]);
            KPs[(wr + lg + 8) * QS_STRIDE + c]     = f2tf32(sacc[nt][2]);
            KPs[(wr + lg + 8) * QS_STRIDE + c + 1] = f2tf32(sacc[nt][3]);
        }
        __syncwarp();

        #pragma unroll
        for (int ks = 0; ks < 8; ks++) {
            int kb = ks * 8;
            unsigned af[4];
            af[0] = KPs[(wr + lg)     * QS_STRIDE + kb + lq];
            af[1] = KPs[(wr + lg + 8) * QS_STRIDE + kb + lq];
            af[2] = KPs[(wr + lg)     * QS_STRIDE + kb + lq + 4];
            af[3] = KPs[(wr + lg + 8) * QS_STRIDE + kb + lq + 4];
            #pragma unroll
            for (int nt = 0; nt < 8; nt++) {
                unsigned bf[2];
                bf[0] = Vs[(kb + lq)     * VS_STRIDE + nt * 8 + lg];
                bf[1] = Vs[(kb + lq + 4) * VS_STRIDE + nt * 8 + lg];
                mma_tf32(oacc[nt], af, bf);
            }
        }
    }

    float inv0 = 1.0f / fmaxf(l0, 1e-30f);
    float inv1 = 1.0f / fmaxf(l1, 1e-30f);
    int r0 = q0 + wr + lg;
    int r1 = r0 + 8;
    #pragma unroll
    for (int nt = 0; nt < 8; nt++) {
        int c = nt * 8 + 2 * lq;
        if (r0 < LL)
            *(float2*)&attout[((size_t)(b * LL + r0)) * HH + h * DHH + c] =
                make_float2(oacc[nt][0] * inv0, oacc[nt][1] * inv0);
        if (r1 < LL)
            *(float2*)&attout[((size_t)(b * LL + r1)) * HH + h * DHH + c] =
                make_float2(oacc[nt][2] * inv1, oacc[nt][3] * inv1);
    }
}

// ---------------------------------------------------------------------------
// Launch
// ---------------------------------------------------------------------------
extern "C" void kernel_launch(void* const* d_in, const int* in_sizes, int n_in,
                              void* d_out, int out_size) {
    const float* x         = (const float*)d_in[0];
    const int*   mask      = (const int*)  d_in[1];
    const float* conv_ln_g = (const float*)d_in[2];
    const float* conv_ln_b = (const float*)d_in[3];
    const float* dw_w      = (const float*)d_in[4];
    const float* dw_b      = (const float*)d_in[5];
    const float* pw_w      = (const float*)d_in[6];
    const float* pw_b      = (const float*)d_in[7];
    const float* att_ln_g  = (const float*)d_in[8];
    const float* att_ln_b  = (const float*)d_in[9];
    const float* qkv_w     = (const float*)d_in[10];
    const float* qkv_b     = (const float*)d_in[11];
    const float* out_w     = (const float*)d_in[12];
    const float* out_b     = (const float*)d_in[13];
    const float* ff_ln_g   = (const float*)d_in[14];
    const float* ff_ln_b   = (const float*)d_in[15];
    const float* ff_w      = (const float*)d_in[16];
    const float* ff_b      = (const float*)d_in[17];
    float* out = (float*)d_out;

    float *norm, *dwout, *qkv, *attout;
    cudaGetSymbolAddress((void**)&norm,   g_norm);
    cudaGetSymbolAddress((void**)&dwout,  g_dwout);
    cudaGetSymbolAddress((void**)&qkv,    g_qkv);
    cudaGetSymbolAddress((void**)&attout, g_attout);

    cudaFuncSetAttribute(flash_kernel,
                         cudaFuncAttributeMaxDynamicSharedMemorySize, FLASH_SMEM);

    const int elems = MM * HH;

    add_pe_kernel<<<(elems + 255) / 256, 256>>>(x, out);

    for (int i = 0; i < NCC; i++) {
        ln_kernel<<<MM, 128>>>(out, norm, conv_ln_g + i * HH, conv_ln_b + i * HH);
        dwconv_kernel<<<(elems + 255) / 256, 256>>>(norm, dwout,
                                                    dw_w + i * HH * KW, dw_b + i * HH);
        gemm_tf32_kernel<true, true><<<dim3(HH / 128, MM / 128), 256>>>(
            dwout, pw_w + (size_t)i * HH * HH, pw_b + i * HH, out, out, MM, HH, HH);
    }

    ln_kernel<<<MM, 128>>>(out, norm, att_ln_g, att_ln_b);
    gemm_tf32_kernel<false, false><<<dim3(H3 / 128, MM / 128), 256>>>(
        norm, qkv_w, qkv_b, nullptr, qkv, MM, H3, HH);

    flash_kernel<<<dim3(BB * NHH, (LL + 63) / 64), 128, FLASH_SMEM>>>(qkv, mask, attout);

    gemm_tf32_kernel<false, true><<<dim3(HH / 128, MM / 128), 256>>>(
        attout, out_w, out_b, out, out, MM, HH, HH);

    ln_kernel<<<MM, 128>>>(out, norm, ff_ln_g, ff_ln_b);
    gemm_tf32_kernel<true, true><<<dim3(HH / 128, MM / 128), 256>>>(
        norm, ff_w, ff_b, out, out, MM, HH, HH);
}